// round 8
// baseline (speedup 1.0000x reference)
#include <cuda_runtime.h>
#include <cuda_fp16.h>
#include <math.h>
#include <stdint.h>

// ---------------- problem constants ----------------
#define FRAMES 4096      // B*T
#define HW     121
#define FCK    7744
#define XSTRIDE 72       // X row stride in fp16 elems -> 144B, conflict-free
#define XROWS   172      // 13x13=169 plane + overread pad
#define BFRAGS  9216     // uint2 fragments per layer: 9 taps*4 ks*8 n*32 lanes
#define HALF0_FRAGS 5120 // taps 0-4
#define HALF1_FRAGS 4096 // taps 5-8
#define RING_BYTES  40960 // max half size in bytes (5120 uint2)
#define FC_KS   484      // 7744/16
#define FC_SPLITS 4
#define FC_KS_PER 121    // 484/4

// conv smem offsets (bytes)
#define SM_X     0
#define SM_RING0 24768
#define SM_RING1 (SM_RING0 + RING_BYTES)          // 65728
#define SM_BIAS  (SM_RING1 + RING_BYTES)          // 106688
#define SM_TOTAL (SM_BIAS + 256)                  // 106944

// ---------------- global scratch ----------------
__device__ __half g_conv_out[(size_t)FRAMES * FCK];
__device__ float g_fc_part[(size_t)FC_SPLITS * FRAMES * 64];
__device__ float g_xg[(size_t)FRAMES * 256];
__device__ float g_lstm[(size_t)FRAMES * 64];
__device__ uint2 g_bf[8 * BFRAGS];            // conv weight B-fragments (fp16)
__device__ uint4 g_wfc[FC_KS * 8 * 32];       // FC weight frags: hi(x,y) lo(z,w)

// ---------------- helpers ----------------
__device__ __forceinline__ uint32_t smem_u32(const void* p) {
    uint32_t a;
    asm("{ .reg .u64 t; cvta.to.shared.u64 t, %1; cvt.u32.u64 %0, t; }" : "=r"(a) : "l"(p));
    return a;
}
__device__ __forceinline__ unsigned pack_half2(__half a, __half b) {
    return (unsigned)__half_as_ushort(a) | ((unsigned)__half_as_ushort(b) << 16);
}
__device__ __forceinline__ void mma_f16(float* d, unsigned a0, unsigned a1,
                                        unsigned a2, unsigned a3,
                                        unsigned b0, unsigned b1) {
    asm volatile("mma.sync.aligned.m16n8k16.row.col.f32.f16.f16.f32 "
                 "{%0,%1,%2,%3},{%4,%5,%6,%7},{%8,%9},{%0,%1,%2,%3};\n"
                 : "+f"(d[0]), "+f"(d[1]), "+f"(d[2]), "+f"(d[3])
                 : "r"(a0), "r"(a1), "r"(a2), "r"(a3), "r"(b0), "r"(b1));
}
__device__ __forceinline__ void cp16(uint32_t dst, const void* src) {
    asm volatile("cp.async.cg.shared.global [%0], [%1], 16;" :: "r"(dst), "l"(src));
}
__device__ __forceinline__ void cp_commit() {
    asm volatile("cp.async.commit_group;" ::: "memory");
}
template <int N>
__device__ __forceinline__ void cp_wait() {
    asm volatile("cp.async.wait_group %0;" :: "n"(N) : "memory");
}
__device__ __forceinline__ float fast_sigmoid(float x) {
    return __fdividef(1.f, 1.f + __expf(-x));
}
__device__ __forceinline__ float fast_tanh(float x) {
    return 1.f - __fdividef(2.f, __expf(2.f * x) + 1.f);
}

// =====================================================================
// Kernel 0a: conv weights -> mma B-fragments (fp16)
// =====================================================================
__global__ void bfrag_prep(const float* __restrict__ c0w, const float* __restrict__ cws)
{
    int t = blockIdx.x * 256 + threadIdx.x;
    if (t >= 8 * BFRAGS) return;
    int lane = t & 31;
    int n    = (t >> 5) & 7;
    int ks   = (t >> 8) & 3;
    int tap  = (t >> 10) % 9;
    int L    = t / BFRAGS;
    int oc   = n * 8 + (lane >> 2);
    int ic0  = ks * 16 + 2 * (lane & 3);

    __half h[4];
#pragma unroll
    for (int e = 0; e < 4; ++e) {
        int ic = ic0 + (e >> 1) * 8 + (e & 1);
        float v = 0.f;
        if (L == 0) {
            if (ks == 0 && ic < 9) v = c0w[oc * 81 + ic * 9 + tap];
        } else {
            v = cws[(size_t)(L - 1) * 36864 + oc * 576 + ic * 9 + tap];
        }
        h[e] = __float2half(v);
    }
    g_bf[t] = make_uint2(pack_half2(h[0], h[1]), pack_half2(h[2], h[3]));
}

// =====================================================================
// Kernel 0b: FC weights -> mma B-fragments, hi/lo fp16 split
// =====================================================================
__global__ void wfrag_prep(const float* __restrict__ fcw)
{
    int t = blockIdx.x * 256 + threadIdx.x;
    if (t >= FC_KS * 8 * 32) return;
    int lane = t & 31;
    int n    = (t >> 5) & 7;
    int ks   = t >> 8;
    int oc   = n * 8 + (lane >> 2);
    int k0   = ks * 16 + 2 * (lane & 3);

    __half h[4], lo[4];
#pragma unroll
    for (int e = 0; e < 4; ++e) {
        int k = k0 + (e >> 1) * 8 + (e & 1);
        float v = fcw[(size_t)oc * FCK + k];
        h[e]  = __float2half(v);
        lo[e] = __float2half(v - __half2float(h[e]));
    }
    g_wfc[t] = make_uint4(pack_half2(h[0], h[1]), pack_half2(h[2], h[3]),
                          pack_half2(lo[0], lo[1]), pack_half2(lo[2], lo[3]));
}

// =====================================================================
// Kernel 1: fused 8-layer conv stack, mma.sync fp16 with cp.async
// half-layer B-staging ring (2 x 40KB). 1 CTA / frame, 9 warps.
// Chunks c = L*2 + half; half0 = taps 0-4, half1 = taps 5-8.
// =====================================================================
__global__ __launch_bounds__(288, 2)
void conv_mma_kernel(const float* __restrict__ x,
                     const float* __restrict__ c0b, const float* __restrict__ cbs)
{
    extern __shared__ char smraw[];
    __half* Xh = (__half*)(smraw + SM_X);
    uint2* ring[2] = { (uint2*)(smraw + SM_RING0), (uint2*)(smraw + SM_RING1) };
    float* bias = (float*)(smraw + SM_BIAS);
    const uint32_t ring_u32[2] = { smem_u32(smraw + SM_RING0), smem_u32(smraw + SM_RING1) };

    const int f    = blockIdx.x;
    const int tid  = threadIdx.x;
    const int warp = tid >> 5;
    const int lane = tid & 31;
    const int qid  = lane >> 2;
    const int tq   = lane & 3;

    // stage chunk 0 (layer 0, taps 0-4) first for overlap with X init
    {
        const uint4* src = (const uint4*)(g_bf);
        for (int i = tid; i < HALF0_FRAGS / 2; i += 288)
            cp16(ring_u32[0] + i * 16, src + i);
        cp_commit();
    }

    // zero X plane
    {
        unsigned* Xz = (unsigned*)Xh;
        for (int i = tid; i < XROWS * XSTRIDE / 2; i += 288) Xz[i] = 0u;
    }
    __syncthreads();

    // load input frame: 9 channels into padded interior
    const float* xf = x + (size_t)f * 9 * HW;
    for (int i = tid; i < 9 * HW; i += 288) {
        int ic = i / HW, pix = i % HW;
        int row = 13 * (pix / 11) + (pix % 11) + 14;
        Xh[row * XSTRIDE + ic] = __float2half(xf[i]);
    }
    __half* gout = g_conv_out + (size_t)f * FCK;

    float acc[8][4];

    for (int c = 0; c < 16; ++c) {
        const int L = c >> 1, half = c & 1, buf = c & 1;

        // stage chunk c+1 into the other ring slot
        if (c + 1 < 16) {
            const int Ln = (c + 1) >> 1, hn = (c + 1) & 1;
            const uint4* src = (const uint4*)(g_bf + (size_t)Ln * BFRAGS
                                              + (hn ? HALF0_FRAGS : 0));
            const int n16 = (hn ? HALF1_FRAGS : HALF0_FRAGS) / 2;
            const uint32_t dst = ring_u32[1 - buf];
            for (int i = tid; i < n16; i += 288) cp16(dst + i * 16, src + i);
            cp_commit();
            cp_wait<1>();   // chunk c arrived
        } else {
            cp_wait<0>();
        }
        if (half == 0 && tid < 64)
            bias[tid] = (L == 0) ? c0b[tid] : cbs[(L - 1) * 64 + tid];
        __syncthreads();

        if (half == 0) {
#pragma unroll
            for (int n = 0; n < 8; ++n) {
                float b0 = bias[n * 8 + 2 * tq], b1 = bias[n * 8 + 2 * tq + 1];
                acc[n][0] = b0; acc[n][1] = b1; acc[n][2] = b0; acc[n][3] = b1;
            }
        }

        const int KS = (L == 0) ? 1 : 4;
        const int tap0 = half ? 5 : 0;
        const int ntap = half ? 4 : 5;
        const uint2* rb = ring[buf];

        for (int t = 0; t < ntap; ++t) {
            const int tap = tap0 + t;
            const int off = 13 * (tap / 3) + (tap % 3);
            const int r0 = 16 * warp + off + qid;
            for (int ks = 0; ks < KS; ++ks) {
                const __half* ph = Xh + r0 * XSTRIDE + (ks * 16 + 2 * tq);
                unsigned a0 = *(const unsigned*)(ph);
                unsigned a1 = *(const unsigned*)(ph + 8 * XSTRIDE);
                unsigned a2 = *(const unsigned*)(ph + 8);
                unsigned a3 = *(const unsigned*)(ph + 8 * XSTRIDE + 8);

                const uint2* bp = rb + ((t * 4 + ks) * 8) * 32 + lane;
#pragma unroll
                for (int n = 0; n < 8; ++n) {
                    uint2 b = bp[n * 32];
                    mma_f16(acc[n], a0, a1, a2, a3, b.x, b.y);
                }
            }
        }

        if (half == 1) {
            __syncthreads();  // all X reads of this layer complete
#pragma unroll
            for (int n = 0; n < 8; ++n) {
                const int oc0 = n * 8 + 2 * tq;
#pragma unroll
                for (int hf = 0; hf < 2; ++hf) {
                    int ob = 16 * warp + qid + 8 * hf;
                    int cc = ob % 13, rr = ob / 13;
                    if (ob <= 140 && cc <= 10) {
                        float v0 = fmaxf(acc[n][2 * hf], 0.f);
                        float v1 = fmaxf(acc[n][2 * hf + 1], 0.f);
                        __half h0 = __float2half(v0);
                        __half h1 = __float2half(v1);
                        if (L < 7) {
                            *(unsigned*)(Xh + (ob + 14) * XSTRIDE + oc0) = pack_half2(h0, h1);
                        } else {
                            gout[oc0 * HW + rr * 11 + cc] = h0;
                            gout[(oc0 + 1) * HW + rr * 11 + cc] = h1;
                        }
                    }
                }
            }
        }
        __syncthreads();
    }
}

// =====================================================================
// Kernel 2: FC GEMM, split-K x4. A double-buffered smem; B fragments
// loaded gmem->register with 1-chunk prefetch (no smem for B).
// =====================================================================
__global__ __launch_bounds__(256)
void fc_mma_kernel()
{
    __shared__ __half As[2][32][24];   // 16 K-cols + pad

    const int m0 = blockIdx.x * 32;
    const int split = blockIdx.y;
    const int ks0 = split * FC_KS_PER;
    const int tid = threadIdx.x;
    const int warp = tid >> 5, lane = tid & 31;
    const int mt = warp >> 2, nq = warp & 3;
    const int qid = lane >> 2, tq = lane & 3;

    const int ar = tid >> 1, ap = tid & 1;   // A loader: threads 0..63
    const int n0 = nq * 2, n1 = n0 + 1;

    float acc[2][4] = {};
    uint4 a_reg;
    uint4 bc0, bc1, bn0, bn1;

    // preload chunk 0
    if (tid < 64) {
        a_reg = *(const uint4*)&g_conv_out[(size_t)(m0 + ar) * FCK + ks0 * 16 + ap * 8];
        *(uint4*)&As[0][ar][ap * 8] = a_reg;
    }
    bc0 = g_wfc[(size_t)ks0 * 256 + n0 * 32 + lane];
    bc1 = g_wfc[(size_t)ks0 * 256 + n1 * 32 + lane];
    __syncthreads();

    for (int i = 0; i < FC_KS_PER; ++i) {
        const int buf = i & 1;
        // prefetch chunk i+1
        if (i + 1 < FC_KS_PER) {
            const int ks = ks0 + i + 1;
            if (tid < 64)
                a_reg = *(const uint4*)&g_conv_out[(size_t)(m0 + ar) * FCK + ks * 16 + ap * 8];
            bn0 = g_wfc[(size_t)ks * 256 + n0 * 32 + lane];
            bn1 = g_wfc[(size_t)ks * 256 + n1 * 32 + lane];
        }
        // mma on chunk i
        {
            const int r0 = mt * 16 + qid;
            const int cb = 2 * tq;
            unsigned a0 = *(const unsigned*)&As[buf][r0][cb];
            unsigned a1 = *(const unsigned*)&As[buf][r0 + 8][cb];
            unsigned a2 = *(const unsigned*)&As[buf][r0][cb + 8];
            unsigned a3 = *(const unsigned*)&As[buf][r0 + 8][cb + 8];
            mma_f16(acc[0], a0, a1, a2, a3, bc0.x, bc0.y);
            mma_f16(acc[0], a0, a1, a2, a3, bc0.z, bc0.w);
            mma_f16(acc[1], a0, a1, a2, a3, bc1.x, bc1.y);
            mma_f16(acc[1], a0, a1, a2, a3, bc1.z, bc1.w);
        }
        if (i + 1 < FC_KS_PER) {
            if (tid < 64) *(uint4*)&As[1 - buf][ar][ap * 8] = a_reg;
            bc0 = bn0; bc1 = bn1;
        }
        __syncthreads();
    }

    // epilogue: raw partial sums
    float* dst = g_fc_part + (size_t)split * FRAMES * 64;
#pragma unroll
    for (int j = 0; j < 2; ++j) {
        const int col = (nq * 2 + j) * 8 + 2 * tq;
#pragma unroll
        for (int hf = 0; hf < 2; ++hf) {
            int m = m0 + mt * 16 + qid + 8 * hf;
            dst[(size_t)m * 64 + col]     = acc[j][2 * hf];
            dst[(size_t)m * 64 + col + 1] = acc[j][2 * hf + 1];
        }
    }
}

// =====================================================================
// Kernel 3: xg = relu(sum(fc partials) + fc_b) @ w_ih^T + b_ih + b_hh
// 128 CTAs x 32 frames.
// =====================================================================
__global__ __launch_bounds__(256)
void xgates_kernel(const float* __restrict__ w_ih, const float* __restrict__ fc_b,
                   const float* __restrict__ b_ih, const float* __restrict__ b_hh)
{
    __shared__ float fs[32][64];
    const int f0 = blockIdx.x * 32;
    const int g = threadIdx.x;
    float w[64];
#pragma unroll
    for (int k = 0; k < 64; ++k) w[k] = w_ih[g * 64 + k];
    for (int i = g; i < 32 * 64; i += 256) {
        size_t idx = (size_t)f0 * 64 + i;
        float v = g_fc_part[idx]
                + g_fc_part[(size_t)FRAMES * 64 + idx]
                + g_fc_part[(size_t)2 * FRAMES * 64 + idx]
                + g_fc_part[(size_t)3 * FRAMES * 64 + idx]
                + fc_b[i % 64];
        fs[i / 64][i % 64] = fmaxf(v, 0.f);
    }
    __syncthreads();
    const float bias = b_ih[g] + b_hh[g];
    for (int f = 0; f < 32; ++f) {
        float s = bias;
#pragma unroll
        for (int k = 0; k < 64; ++k) s = fmaf(w[k], fs[f][k], s);
        g_xg[(size_t)(f0 + f) * 256 + g] = s;
    }
}

// =====================================================================
// Kernel 4: recurrent LSTM. 32 CTAs, 512 threads; gate dot split over 2 lanes.
// =====================================================================
__global__ __launch_bounds__(512)
void lstm_kernel(const float* __restrict__ w_hh)
{
    __shared__ float h_s[64];
    __shared__ float g_s[256];
    const int b = blockIdx.x;
    const int tid = threadIdx.x;
    const int g = tid >> 1, hh = tid & 1;

    float w[32];
#pragma unroll
    for (int k = 0; k < 32; ++k) w[k] = w_hh[g * 64 + hh * 32 + k];
    float c = 0.f;
    if (tid < 64) h_s[tid] = 0.f;
    __syncthreads();

    const float* xgb = g_xg + (size_t)b * 128 * 256;
    float* lob = g_lstm + (size_t)b * 128 * 64;

    float xnext = (hh == 0) ? xgb[g] : 0.f;
    for (int t = 0; t < 128; ++t) {
        float s1 = 0.f, s2 = 0.f;
        const float* hp = h_s + hh * 32;
#pragma unroll
        for (int k = 0; k < 16; ++k) {
            s1 = fmaf(w[k], hp[k], s1);
            s2 = fmaf(w[k + 16], hp[k + 16], s2);
        }
        float s = xnext + s1 + s2;
        s += __shfl_xor_sync(0xffffffffu, s, 1);
        if (hh == 0) {
            g_s[g] = s;
            if (t < 127) xnext = xgb[(t + 1) * 256 + g];
        }
        __syncthreads();
        if (tid < 64) {
            float ig = fast_sigmoid(g_s[tid]);
            float fg = fast_sigmoid(g_s[64 + tid]);
            float gg = fast_tanh(g_s[128 + tid]);
            float og = fast_sigmoid(g_s[192 + tid]);
            c = fg * c + ig * gg;
            float h = og * fast_tanh(c);
            lob[t * 64 + tid] = h;
            h_s[tid] = h;
        }
        __syncthreads();
    }
}

// =====================================================================
// Kernel 5: fused policy/value heads
// =====================================================================
__global__ __launch_bounds__(256)
void heads_kernel(const float* __restrict__ p1w, const float* __restrict__ p1b,
                  const float* __restrict__ p2w, const float* __restrict__ p2b,
                  const float* __restrict__ v1w, const float* __restrict__ v1b,
                  const float* __restrict__ v2w, const float* __restrict__ v2b,
                  float* __restrict__ out)
{
    __shared__ float h_s[32][64];
    __shared__ float p2s[6 * 128];
    __shared__ float v2s[128];
    __shared__ float u_s[256];

    const int f0 = blockIdx.x * 32;
    const int t = threadIdx.x;

    const float* wsrc = (t < 128) ? (p1w + t * 64) : (v1w + (t - 128) * 64);
    float w[64];
#pragma unroll
    for (int k = 0; k < 64; ++k) w[k] = wsrc[k];
    const float bias = (t < 128) ? p1b[t] : v1b[t - 128];

    for (int i = t; i < 32 * 64; i += 256) h_s[i / 64][i % 64] = g_lstm[(size_t)f0 * 64 + i];
    for (int i = t; i < 768; i += 256) p2s[i] = p2w[i];
    if (t < 128) v2s[t] = v2w[t];
    __syncthreads();

    const int warp = t >> 5, lane = t & 31;
    for (int fi = 0; fi < 32; ++fi) {
        float s = bias;
#pragma unroll
        for (int k = 0; k < 64; ++k) s = fmaf(w[k], h_s[fi][k], s);
        u_s[t] = fmaxf(s, 0.f);
        __syncthreads();

        const int f = f0 + fi;
        if (warp < 6) {
            float s2 = 0.f;
#pragma unroll
            for (int j = 0; j < 4; ++j)
                s2 = fmaf(p2s[warp * 128 + j * 32 + lane], u_s[j * 32 + lane], s2);
            for (int off = 16; off; off >>= 1) s2 += __shfl_down_sync(0xffffffffu, s2, off);
            if (lane == 0) out[f * 6 + warp] = s2 + p2b[warp];
        } else if (warp == 6) {
            float s2 = 0.f;
#pragma unroll
            for (int j = 0; j < 4; ++j)
                s2 = fmaf(v2s[j * 32 + lane], u_s[128 + j * 32 + lane], s2);
            for (int off = 16; off; off >>= 1) s2 += __shfl_down_sync(0xffffffffu, s2, off);
            if (lane == 0) out[FRAMES * 6 + f] = s2 + v2b[0];
        }
        __syncthreads();
    }
}

// =====================================================================
extern "C" void kernel_launch(void* const* d_in, const int* in_sizes, int n_in,
                              void* d_out, int out_size)
{
    const float* x    = (const float*)d_in[0];
    const float* c0w  = (const float*)d_in[1];
    const float* c0b  = (const float*)d_in[2];
    const float* cws  = (const float*)d_in[3];
    const float* cbs  = (const float*)d_in[4];
    const float* fcw  = (const float*)d_in[5];
    const float* fcb  = (const float*)d_in[6];
    const float* wih  = (const float*)d_in[7];
    const float* whh  = (const float*)d_in[8];
    const float* bih  = (const float*)d_in[9];
    const float* bhh  = (const float*)d_in[10];
    const float* p1w  = (const float*)d_in[11];
    const float* p1b  = (const float*)d_in[12];
    const float* p2w  = (const float*)d_in[13];
    const float* p2b  = (const float*)d_in[14];
    const float* v1w  = (const float*)d_in[15];
    const float* v1b  = (const float*)d_in[16];
    const float* v2w  = (const float*)d_in[17];
    const float* v2b  = (const float*)d_in[18];
    float* out = (float*)d_out;

    cudaFuncSetAttribute(conv_mma_kernel,
                         cudaFuncAttributeMaxDynamicSharedMemorySize, SM_TOTAL);

    bfrag_prep<<<288, 256>>>(c0w, cws);
    wfrag_prep<<<(FC_KS * 8 * 32 + 255) / 256, 256>>>(fcw);
    conv_mma_kernel<<<FRAMES, 288, SM_TOTAL>>>(x, c0b, cbs);
    fc_mma_kernel<<<dim3(FRAMES / 32, FC_SPLITS), 256>>>();
    xgates_kernel<<<FRAMES / 32, 256>>>(wih, fcb, bih, bhh);
    lstm_kernel<<<32, 512>>>(whh);
    heads_kernel<<<FRAMES / 32, 256>>>(p1w, p1b, p2w, p2b, v1w, v1b, v2w, v2b, out);
}

// round 9
// speedup vs baseline: 1.1254x; 1.1254x over previous
#include <cuda_runtime.h>
#include <cuda_fp16.h>
#include <math.h>
#include <stdint.h>

// ---------------- problem constants ----------------
#define FRAMES 4096      // B*T
#define HW     121
#define FCK    7744
#define XSTRIDE 72       // X row stride in fp16 elems -> 144B
#define XROWS   172      // 13x13=169 plane + overread pad
#define BFRAGS  9216     // uint2 fragments per layer: 9 taps*4 ks*8 n*32 lanes
#define HALF0_FRAGS 5120 // taps 0-4
#define HALF1_FRAGS 4096 // taps 5-8
#define RING_BYTES  40960
#define FC_KS   484      // 7744/16
#define FC_SPLITS 4
#define FC_KS_PER 121    // 484/4

// conv smem offsets (bytes)
#define SM_X     0
#define SM_RING0 24768
#define SM_RING1 (SM_RING0 + RING_BYTES)          // 65728
#define SM_BIAS  (SM_RING1 + RING_BYTES)          // 106688
#define SM_TOTAL (SM_BIAS + 256)                  // 106944

// ---------------- global scratch ----------------
__device__ __half g_conv_out[(size_t)FRAMES * FCK];
__device__ float g_fc_part[(size_t)FC_SPLITS * FRAMES * 64];
__device__ float g_xg[(size_t)FRAMES * 256];
__device__ float g_lstm[(size_t)FRAMES * 64];
__device__ uint2 g_bf[8 * BFRAGS];            // conv weight B-fragments (fp16)
__device__ uint4 g_wfc[FC_KS * 8 * 32];       // FC weight frags: hi(x,y) lo(z,w)

// ---------------- helpers ----------------
__device__ __forceinline__ uint32_t smem_u32(const void* p) {
    uint32_t a;
    asm("{ .reg .u64 t; cvta.to.shared.u64 t, %1; cvt.u32.u64 %0, t; }" : "=r"(a) : "l"(p));
    return a;
}
__device__ __forceinline__ unsigned pack_half2(__half a, __half b) {
    return (unsigned)__half_as_ushort(a) | ((unsigned)__half_as_ushort(b) << 16);
}
__device__ __forceinline__ void mma_f16(float* d, unsigned a0, unsigned a1,
                                        unsigned a2, unsigned a3,
                                        unsigned b0, unsigned b1) {
    asm volatile("mma.sync.aligned.m16n8k16.row.col.f32.f16.f16.f32 "
                 "{%0,%1,%2,%3},{%4,%5,%6,%7},{%8,%9},{%0,%1,%2,%3};\n"
                 : "+f"(d[0]), "+f"(d[1]), "+f"(d[2]), "+f"(d[3])
                 : "r"(a0), "r"(a1), "r"(a2), "r"(a3), "r"(b0), "r"(b1));
}
__device__ __forceinline__ void cp16(uint32_t dst, const void* src) {
    asm volatile("cp.async.cg.shared.global [%0], [%1], 16;" :: "r"(dst), "l"(src));
}
__device__ __forceinline__ void cp_commit() {
    asm volatile("cp.async.commit_group;" ::: "memory");
}
template <int N>
__device__ __forceinline__ void cp_wait() {
    asm volatile("cp.async.wait_group %0;" :: "n"(N) : "memory");
}
__device__ __forceinline__ float fast_sigmoid(float x) {
    return __fdividef(1.f, 1.f + __expf(-x));
}
__device__ __forceinline__ float fast_tanh(float x) {
    return 1.f - __fdividef(2.f, __expf(2.f * x) + 1.f);
}

// =====================================================================
// Kernel 0a: conv weights -> mma B-fragments (fp16)
// =====================================================================
__global__ void bfrag_prep(const float* __restrict__ c0w, const float* __restrict__ cws)
{
    int t = blockIdx.x * 256 + threadIdx.x;
    if (t >= 8 * BFRAGS) return;
    int lane = t & 31;
    int n    = (t >> 5) & 7;
    int ks   = (t >> 8) & 3;
    int tap  = (t >> 10) % 9;
    int L    = t / BFRAGS;
    int oc   = n * 8 + (lane >> 2);
    int ic0  = ks * 16 + 2 * (lane & 3);

    __half h[4];
#pragma unroll
    for (int e = 0; e < 4; ++e) {
        int ic = ic0 + (e >> 1) * 8 + (e & 1);
        float v = 0.f;
        if (L == 0) {
            if (ks == 0 && ic < 9) v = c0w[oc * 81 + ic * 9 + tap];
        } else {
            v = cws[(size_t)(L - 1) * 36864 + oc * 576 + ic * 9 + tap];
        }
        h[e] = __float2half(v);
    }
    g_bf[t] = make_uint2(pack_half2(h[0], h[1]), pack_half2(h[2], h[3]));
}

// =====================================================================
// Kernel 0b: FC weights -> mma B-fragments, hi/lo fp16 split
// =====================================================================
__global__ void wfrag_prep(const float* __restrict__ fcw)
{
    int t = blockIdx.x * 256 + threadIdx.x;
    if (t >= FC_KS * 8 * 32) return;
    int lane = t & 31;
    int n    = (t >> 5) & 7;
    int ks   = t >> 8;
    int oc   = n * 8 + (lane >> 2);
    int k0   = ks * 16 + 2 * (lane & 3);

    __half h[4], lo[4];
#pragma unroll
    for (int e = 0; e < 4; ++e) {
        int k = k0 + (e >> 1) * 8 + (e & 1);
        float v = fcw[(size_t)oc * FCK + k];
        h[e]  = __float2half(v);
        lo[e] = __float2half(v - __half2float(h[e]));
    }
    g_wfc[t] = make_uint4(pack_half2(h[0], h[1]), pack_half2(h[2], h[3]),
                          pack_half2(lo[0], lo[1]), pack_half2(lo[2], lo[3]));
}

// =====================================================================
// Kernel 1: fused 8-layer conv stack, mma.sync fp16.
// PIXEL-INDEXED M: 8 warps x 16 M-rows = 128 rows for 121 pixels
// (was 9 warps x 16 over padded rows = 16% HMMA waste).
// Each thread owns pixels m_lo = 16*warp+qid, m_hi = m_lo+8 with
// precomputed plane-row bases; conv taps remain a +off row shift.
// cp.async half-layer B ring retained.
// =====================================================================
__global__ __launch_bounds__(256, 2)
void conv_mma_kernel(const float* __restrict__ x,
                     const float* __restrict__ c0b, const float* __restrict__ cbs)
{
    extern __shared__ char smraw[];
    __half* Xh = (__half*)(smraw + SM_X);
    uint2* ring[2] = { (uint2*)(smraw + SM_RING0), (uint2*)(smraw + SM_RING1) };
    float* bias = (float*)(smraw + SM_BIAS);
    const uint32_t ring_u32[2] = { smem_u32(smraw + SM_RING0), smem_u32(smraw + SM_RING1) };

    const int f    = blockIdx.x;
    const int tid  = threadIdx.x;
    const int warp = tid >> 5;
    const int lane = tid & 31;
    const int qid  = lane >> 2;
    const int tq   = lane & 3;

    // per-thread pixel rows and plane bases
    const int m_lo = 16 * warp + qid;
    const int m_hi = m_lo + 8;
    const bool v_lo = (m_lo < HW);
    const bool v_hi = (m_hi < HW);
    const int ob_lo = v_lo ? (13 * (m_lo / 11) + (m_lo % 11)) : 143;
    const int ob_hi = v_hi ? (13 * (m_hi / 11) + (m_hi % 11)) : 143;

    // stage chunk 0 (layer 0, taps 0-4)
    {
        const uint4* src = (const uint4*)(g_bf);
        for (int i = tid; i < HALF0_FRAGS / 2; i += 256)
            cp16(ring_u32[0] + i * 16, src + i);
        cp_commit();
    }

    // zero X plane
    {
        unsigned* Xz = (unsigned*)Xh;
        for (int i = tid; i < XROWS * XSTRIDE / 2; i += 256) Xz[i] = 0u;
    }
    __syncthreads();

    // load input frame: 9 channels into padded interior
    const float* xf = x + (size_t)f * 9 * HW;
    for (int i = tid; i < 9 * HW; i += 256) {
        int ic = i / HW, pix = i % HW;
        int row = 13 * (pix / 11) + (pix % 11) + 14;
        Xh[row * XSTRIDE + ic] = __float2half(xf[i]);
    }
    __half* gout = g_conv_out + (size_t)f * FCK;

    float acc[8][4];

    for (int c = 0; c < 16; ++c) {
        const int L = c >> 1, half = c & 1, buf = c & 1;

        // stage chunk c+1 into the other ring slot
        if (c + 1 < 16) {
            const int Ln = (c + 1) >> 1, hn = (c + 1) & 1;
            const uint4* src = (const uint4*)(g_bf + (size_t)Ln * BFRAGS
                                              + (hn ? HALF0_FRAGS : 0));
            const int n16 = (hn ? HALF1_FRAGS : HALF0_FRAGS) / 2;
            const uint32_t dst = ring_u32[1 - buf];
            for (int i = tid; i < n16; i += 256) cp16(dst + i * 16, src + i);
            cp_commit();
            cp_wait<1>();
        } else {
            cp_wait<0>();
        }
        if (half == 0 && tid < 64)
            bias[tid] = (L == 0) ? c0b[tid] : cbs[(L - 1) * 64 + tid];
        __syncthreads();

        if (half == 0) {
#pragma unroll
            for (int n = 0; n < 8; ++n) {
                float b0 = bias[n * 8 + 2 * tq], b1 = bias[n * 8 + 2 * tq + 1];
                acc[n][0] = b0; acc[n][1] = b1; acc[n][2] = b0; acc[n][3] = b1;
            }
        }

        const int KS = (L == 0) ? 1 : 4;
        const int tap0 = half ? 5 : 0;
        const int ntap = half ? 4 : 5;
        const uint2* rb = ring[buf];

        for (int t = 0; t < ntap; ++t) {
            const int tap = tap0 + t;
            const int off = 13 * (tap / 3) + (tap % 3);
            const __half* plo_base = Xh + (ob_lo + off) * XSTRIDE;
            const __half* phi_base = Xh + (ob_hi + off) * XSTRIDE;
            for (int ks = 0; ks < KS; ++ks) {
                const int cb = ks * 16 + 2 * tq;
                unsigned a0 = *(const unsigned*)(plo_base + cb);
                unsigned a1 = *(const unsigned*)(phi_base + cb);
                unsigned a2 = *(const unsigned*)(plo_base + cb + 8);
                unsigned a3 = *(const unsigned*)(phi_base + cb + 8);

                const uint2* bp = rb + ((t * 4 + ks) * 8) * 32 + lane;
#pragma unroll
                for (int n = 0; n < 8; ++n) {
                    uint2 b = bp[n * 32];
                    mma_f16(acc[n], a0, a1, a2, a3, b.x, b.y);
                }
            }
        }

        if (half == 1) {
            __syncthreads();  // all X reads of this layer complete
#pragma unroll
            for (int n = 0; n < 8; ++n) {
                const int oc0 = n * 8 + 2 * tq;
                if (v_lo) {
                    float v0 = fmaxf(acc[n][0], 0.f);
                    float v1 = fmaxf(acc[n][1], 0.f);
                    __half h0 = __float2half(v0);
                    __half h1 = __float2half(v1);
                    if (L < 7) {
                        *(unsigned*)(Xh + (ob_lo + 14) * XSTRIDE + oc0) = pack_half2(h0, h1);
                    } else {
                        gout[oc0 * HW + m_lo] = h0;
                        gout[(oc0 + 1) * HW + m_lo] = h1;
                    }
                }
                if (v_hi) {
                    float v0 = fmaxf(acc[n][2], 0.f);
                    float v1 = fmaxf(acc[n][3], 0.f);
                    __half h0 = __float2half(v0);
                    __half h1 = __float2half(v1);
                    if (L < 7) {
                        *(unsigned*)(Xh + (ob_hi + 14) * XSTRIDE + oc0) = pack_half2(h0, h1);
                    } else {
                        gout[oc0 * HW + m_hi] = h0;
                        gout[(oc0 + 1) * HW + m_hi] = h1;
                    }
                }
            }
        }
        __syncthreads();
    }
}

// =====================================================================
// Kernel 2: FC GEMM, split-K x4. A double-buffered smem; B fragments
// gmem->register with 1-chunk prefetch.
// =====================================================================
__global__ __launch_bounds__(256)
void fc_mma_kernel()
{
    __shared__ __half As[2][32][24];

    const int m0 = blockIdx.x * 32;
    const int split = blockIdx.y;
    const int ks0 = split * FC_KS_PER;
    const int tid = threadIdx.x;
    const int warp = tid >> 5, lane = tid & 31;
    const int mt = warp >> 2, nq = warp & 3;
    const int qid = lane >> 2, tq = lane & 3;

    const int ar = tid >> 1, ap = tid & 1;
    const int n0 = nq * 2, n1 = n0 + 1;

    float acc[2][4] = {};
    uint4 a_reg;
    uint4 bc0, bc1, bn0, bn1;

    if (tid < 64) {
        a_reg = *(const uint4*)&g_conv_out[(size_t)(m0 + ar) * FCK + ks0 * 16 + ap * 8];
        *(uint4*)&As[0][ar][ap * 8] = a_reg;
    }
    bc0 = g_wfc[(size_t)ks0 * 256 + n0 * 32 + lane];
    bc1 = g_wfc[(size_t)ks0 * 256 + n1 * 32 + lane];
    __syncthreads();

    for (int i = 0; i < FC_KS_PER; ++i) {
        const int buf = i & 1;
        if (i + 1 < FC_KS_PER) {
            const int ks = ks0 + i + 1;
            if (tid < 64)
                a_reg = *(const uint4*)&g_conv_out[(size_t)(m0 + ar) * FCK + ks * 16 + ap * 8];
            bn0 = g_wfc[(size_t)ks * 256 + n0 * 32 + lane];
            bn1 = g_wfc[(size_t)ks * 256 + n1 * 32 + lane];
        }
        {
            const int r0 = mt * 16 + qid;
            const int cb = 2 * tq;
            unsigned a0 = *(const unsigned*)&As[buf][r0][cb];
            unsigned a1 = *(const unsigned*)&As[buf][r0 + 8][cb];
            unsigned a2 = *(const unsigned*)&As[buf][r0][cb + 8];
            unsigned a3 = *(const unsigned*)&As[buf][r0 + 8][cb + 8];
            mma_f16(acc[0], a0, a1, a2, a3, bc0.x, bc0.y);
            mma_f16(acc[0], a0, a1, a2, a3, bc0.z, bc0.w);
            mma_f16(acc[1], a0, a1, a2, a3, bc1.x, bc1.y);
            mma_f16(acc[1], a0, a1, a2, a3, bc1.z, bc1.w);
        }
        if (i + 1 < FC_KS_PER) {
            if (tid < 64) *(uint4*)&As[1 - buf][ar][ap * 8] = a_reg;
            bc0 = bn0; bc1 = bn1;
        }
        __syncthreads();
    }

    float* dst = g_fc_part + (size_t)split * FRAMES * 64;
#pragma unroll
    for (int j = 0; j < 2; ++j) {
        const int col = (nq * 2 + j) * 8 + 2 * tq;
#pragma unroll
        for (int hf = 0; hf < 2; ++hf) {
            int m = m0 + mt * 16 + qid + 8 * hf;
            dst[(size_t)m * 64 + col]     = acc[j][2 * hf];
            dst[(size_t)m * 64 + col + 1] = acc[j][2 * hf + 1];
        }
    }
}

// =====================================================================
// Kernel 3: xg = relu(sum(fc partials) + fc_b) @ w_ih^T + b_ih + b_hh
// =====================================================================
__global__ __launch_bounds__(256)
void xgates_kernel(const float* __restrict__ w_ih, const float* __restrict__ fc_b,
                   const float* __restrict__ b_ih, const float* __restrict__ b_hh)
{
    __shared__ float fs[32][64];
    const int f0 = blockIdx.x * 32;
    const int g = threadIdx.x;
    float w[64];
#pragma unroll
    for (int k = 0; k < 64; ++k) w[k] = w_ih[g * 64 + k];
    for (int i = g; i < 32 * 64; i += 256) {
        size_t idx = (size_t)f0 * 64 + i;
        float v = g_fc_part[idx]
                + g_fc_part[(size_t)FRAMES * 64 + idx]
                + g_fc_part[(size_t)2 * FRAMES * 64 + idx]
                + g_fc_part[(size_t)3 * FRAMES * 64 + idx]
                + fc_b[i % 64];
        fs[i / 64][i % 64] = fmaxf(v, 0.f);
    }
    __syncthreads();
    const float bias = b_ih[g] + b_hh[g];
    for (int f = 0; f < 32; ++f) {
        float s = bias;
#pragma unroll
        for (int k = 0; k < 64; ++k) s = fmaf(w[k], fs[f][k], s);
        g_xg[(size_t)(f0 + f) * 256 + g] = s;
    }
}

// =====================================================================
// Kernel 4: recurrent LSTM. 32 CTAs, 512 threads.
// =====================================================================
__global__ __launch_bounds__(512)
void lstm_kernel(const float* __restrict__ w_hh)
{
    __shared__ float h_s[64];
    __shared__ float g_s[256];
    const int b = blockIdx.x;
    const int tid = threadIdx.x;
    const int g = tid >> 1, hh = tid & 1;

    float w[32];
#pragma unroll
    for (int k = 0; k < 32; ++k) w[k] = w_hh[g * 64 + hh * 32 + k];
    float c = 0.f;
    if (tid < 64) h_s[tid] = 0.f;
    __syncthreads();

    const float* xgb = g_xg + (size_t)b * 128 * 256;
    float* lob = g_lstm + (size_t)b * 128 * 64;

    float xnext = (hh == 0) ? xgb[g] : 0.f;
    for (int t = 0; t < 128; ++t) {
        float s1 = 0.f, s2 = 0.f;
        const float* hp = h_s + hh * 32;
#pragma unroll
        for (int k = 0; k < 16; ++k) {
            s1 = fmaf(w[k], hp[k], s1);
            s2 = fmaf(w[k + 16], hp[k + 16], s2);
        }
        float s = xnext + s1 + s2;
        s += __shfl_xor_sync(0xffffffffu, s, 1);
        if (hh == 0) {
            g_s[g] = s;
            if (t < 127) xnext = xgb[(t + 1) * 256 + g];
        }
        __syncthreads();
        if (tid < 64) {
            float ig = fast_sigmoid(g_s[tid]);
            float fg = fast_sigmoid(g_s[64 + tid]);
            float gg = fast_tanh(g_s[128 + tid]);
            float og = fast_sigmoid(g_s[192 + tid]);
            c = fg * c + ig * gg;
            float h = og * fast_tanh(c);
            lob[t * 64 + tid] = h;
            h_s[tid] = h;
        }
        __syncthreads();
    }
}

// =====================================================================
// Kernel 5: fused policy/value heads
// =====================================================================
__global__ __launch_bounds__(256)
void heads_kernel(const float* __restrict__ p1w, const float* __restrict__ p1b,
                  const float* __restrict__ p2w, const float* __restrict__ p2b,
                  const float* __restrict__ v1w, const float* __restrict__ v1b,
                  const float* __restrict__ v2w, const float* __restrict__ v2b,
                  float* __restrict__ out)
{
    __shared__ float h_s[32][64];
    __shared__ float p2s[6 * 128];
    __shared__ float v2s[128];
    __shared__ float u_s[256];

    const int f0 = blockIdx.x * 32;
    const int t = threadIdx.x;

    const float* wsrc = (t < 128) ? (p1w + t * 64) : (v1w + (t - 128) * 64);
    float w[64];
#pragma unroll
    for (int k = 0; k < 64; ++k) w[k] = wsrc[k];
    const float bias = (t < 128) ? p1b[t] : v1b[t - 128];

    for (int i = t; i < 32 * 64; i += 256) h_s[i / 64][i % 64] = g_lstm[(size_t)f0 * 64 + i];
    for (int i = t; i < 768; i += 256) p2s[i] = p2w[i];
    if (t < 128) v2s[t] = v2w[t];
    __syncthreads();

    const int warp = t >> 5, lane = t & 31;
    for (int fi = 0; fi < 32; ++fi) {
        float s = bias;
#pragma unroll
        for (int k = 0; k < 64; ++k) s = fmaf(w[k], h_s[fi][k], s);
        u_s[t] = fmaxf(s, 0.f);
        __syncthreads();

        const int f = f0 + fi;
        if (warp < 6) {
            float s2 = 0.f;
#pragma unroll
            for (int j = 0; j < 4; ++j)
                s2 = fmaf(p2s[warp * 128 + j * 32 + lane], u_s[j * 32 + lane], s2);
            for (int off = 16; off; off >>= 1) s2 += __shfl_down_sync(0xffffffffu, s2, off);
            if (lane == 0) out[f * 6 + warp] = s2 + p2b[warp];
        } else if (warp == 6) {
            float s2 = 0.f;
#pragma unroll
            for (int j = 0; j < 4; ++j)
                s2 = fmaf(v2s[j * 32 + lane], u_s[128 + j * 32 + lane], s2);
            for (int off = 16; off; off >>= 1) s2 += __shfl_down_sync(0xffffffffu, s2, off);
            if (lane == 0) out[FRAMES * 6 + f] = s2 + v2b[0];
        }
        __syncthreads();
    }
}

// =====================================================================
extern "C" void kernel_launch(void* const* d_in, const int* in_sizes, int n_in,
                              void* d_out, int out_size)
{
    const float* x    = (const float*)d_in[0];
    const float* c0w  = (const float*)d_in[1];
    const float* c0b  = (const float*)d_in[2];
    const float* cws  = (const float*)d_in[3];
    const float* cbs  = (const float*)d_in[4];
    const float* fcw  = (const float*)d_in[5];
    const float* fcb  = (const float*)d_in[6];
    const float* wih  = (const float*)d_in[7];
    const float* whh  = (const float*)d_in[8];
    const float* bih  = (const float*)d_in[9];
    const float* bhh  = (const float*)d_in[10];
    const float* p1w  = (const float*)d_in[11];
    const float* p1b  = (const float*)d_in[12];
    const float* p2w  = (const float*)d_in[13];
    const float* p2b  = (const float*)d_in[14];
    const float* v1w  = (const float*)d_in[15];
    const float* v1b  = (const float*)d_in[16];
    const float* v2w  = (const float*)d_in[17];
    const float* v2b  = (const float*)d_in[18];
    float* out = (float*)d_out;

    cudaFuncSetAttribute(conv_mma_kernel,
                         cudaFuncAttributeMaxDynamicSharedMemorySize, SM_TOTAL);

    bfrag_prep<<<288, 256>>>(c0w, cws);
    wfrag_prep<<<(FC_KS * 8 * 32 + 255) / 256, 256>>>(fcw);
    conv_mma_kernel<<<FRAMES, 256, SM_TOTAL>>>(x, c0b, cbs);
    fc_mma_kernel<<<dim3(FRAMES / 32, FC_SPLITS), 256>>>();
    xgates_kernel<<<FRAMES / 32, 256>>>(wih, fcb, bih, bhh);
    lstm_kernel<<<32, 512>>>(whh);
    heads_kernel<<<FRAMES / 32, 256>>>(p1w, p1b, p2w, p2b, v1w, v1b, v2w, v2b, out);
}

// round 10
// speedup vs baseline: 1.1353x; 1.0089x over previous
#include <cuda_runtime.h>
#include <cuda_fp16.h>
#include <math.h>
#include <stdint.h>

// ---------------- problem constants ----------------
#define FRAMES 4096      // B*T
#define HW     121
#define FCK    7744
#define XSTRIDE 72       // X row stride in fp16 elems -> 144B
#define XROWS   172      // 13x13=169 plane + overread pad
#define BFRAGS  9216     // uint2 fragments per layer: 9 taps*4 ks*8 n*32 lanes
#define HALF0_FRAGS 5120 // taps 0-4
#define HALF1_FRAGS 4096 // taps 5-8
#define RING_BYTES  40960
#define FC_KS   484      // 7744/16
#define FC_SPLITS 4
#define FC_KS_PER 121    // 484/4

// conv smem offsets (bytes)
#define SM_X     0
#define SM_RING0 24768
#define SM_RING1 (SM_RING0 + RING_BYTES)          // 65728
#define SM_BIAS  (SM_RING1 + RING_BYTES)          // 106688
#define SM_TOTAL (SM_BIAS + 256)                  // 106944

// ---------------- global scratch ----------------
__device__ __half g_conv_out[(size_t)FRAMES * FCK];
__device__ float g_fc_part[(size_t)FC_SPLITS * FRAMES * 64];
__device__ float g_xg[(size_t)FRAMES * 256];
__device__ float g_lstm[(size_t)FRAMES * 64];
__device__ uint2 g_bf[8 * BFRAGS];            // conv weight B-fragments (fp16)
__device__ uint2 g_wfc[FC_KS * 8 * 32];       // FC weight frags (fp16 hi only)

// ---------------- helpers ----------------
__device__ __forceinline__ uint32_t smem_u32(const void* p) {
    uint32_t a;
    asm("{ .reg .u64 t; cvta.to.shared.u64 t, %1; cvt.u32.u64 %0, t; }" : "=r"(a) : "l"(p));
    return a;
}
__device__ __forceinline__ unsigned pack_half2(__half a, __half b) {
    return (unsigned)__half_as_ushort(a) | ((unsigned)__half_as_ushort(b) << 16);
}
__device__ __forceinline__ void mma_f16(float* d, unsigned a0, unsigned a1,
                                        unsigned a2, unsigned a3,
                                        unsigned b0, unsigned b1) {
    asm volatile("mma.sync.aligned.m16n8k16.row.col.f32.f16.f16.f32 "
                 "{%0,%1,%2,%3},{%4,%5,%6,%7},{%8,%9},{%0,%1,%2,%3};\n"
                 : "+f"(d[0]), "+f"(d[1]), "+f"(d[2]), "+f"(d[3])
                 : "r"(a0), "r"(a1), "r"(a2), "r"(a3), "r"(b0), "r"(b1));
}
__device__ __forceinline__ void cp16(uint32_t dst, const void* src) {
    asm volatile("cp.async.cg.shared.global [%0], [%1], 16;" :: "r"(dst), "l"(src));
}
__device__ __forceinline__ void cp_commit() {
    asm volatile("cp.async.commit_group;" ::: "memory");
}
template <int N>
__device__ __forceinline__ void cp_wait() {
    asm volatile("cp.async.wait_group %0;" :: "n"(N) : "memory");
}
__device__ __forceinline__ float fast_sigmoid(float x) {
    return __fdividef(1.f, 1.f + __expf(-x));
}
__device__ __forceinline__ float fast_tanh(float x) {
    return 1.f - __fdividef(2.f, __expf(2.f * x) + 1.f);
}

// =====================================================================
// Kernel 0a: conv weights -> mma B-fragments (fp16)
// =====================================================================
__global__ void bfrag_prep(const float* __restrict__ c0w, const float* __restrict__ cws)
{
    int t = blockIdx.x * 256 + threadIdx.x;
    if (t >= 8 * BFRAGS) return;
    int lane = t & 31;
    int n    = (t >> 5) & 7;
    int ks   = (t >> 8) & 3;
    int tap  = (t >> 10) % 9;
    int L    = t / BFRAGS;
    int oc   = n * 8 + (lane >> 2);
    int ic0  = ks * 16 + 2 * (lane & 3);

    __half h[4];
#pragma unroll
    for (int e = 0; e < 4; ++e) {
        int ic = ic0 + (e >> 1) * 8 + (e & 1);
        float v = 0.f;
        if (L == 0) {
            if (ks == 0 && ic < 9) v = c0w[oc * 81 + ic * 9 + tap];
        } else {
            v = cws[(size_t)(L - 1) * 36864 + oc * 576 + ic * 9 + tap];
        }
        h[e] = __float2half(v);
    }
    g_bf[t] = make_uint2(pack_half2(h[0], h[1]), pack_half2(h[2], h[3]));
}

// =====================================================================
// Kernel 0b: FC weights -> mma B-fragments (fp16, hi only)
// =====================================================================
__global__ void wfrag_prep(const float* __restrict__ fcw)
{
    int t = blockIdx.x * 256 + threadIdx.x;
    if (t >= FC_KS * 8 * 32) return;
    int lane = t & 31;
    int n    = (t >> 5) & 7;
    int ks   = t >> 8;
    int oc   = n * 8 + (lane >> 2);
    int k0   = ks * 16 + 2 * (lane & 3);

    __half h[4];
#pragma unroll
    for (int e = 0; e < 4; ++e) {
        int k = k0 + (e >> 1) * 8 + (e & 1);
        h[e] = __float2half(fcw[(size_t)oc * FCK + k]);
    }
    g_wfc[t] = make_uint2(pack_half2(h[0], h[1]), pack_half2(h[2], h[3]));
}

// =====================================================================
// Kernel 1: fused 8-layer conv stack, mma.sync fp16, pixel-indexed M.
// (at the HMMA issue floor — unchanged from round 9)
// =====================================================================
__global__ __launch_bounds__(256, 2)
void conv_mma_kernel(const float* __restrict__ x,
                     const float* __restrict__ c0b, const float* __restrict__ cbs)
{
    extern __shared__ char smraw[];
    __half* Xh = (__half*)(smraw + SM_X);
    uint2* ring[2] = { (uint2*)(smraw + SM_RING0), (uint2*)(smraw + SM_RING1) };
    float* bias = (float*)(smraw + SM_BIAS);
    const uint32_t ring_u32[2] = { smem_u32(smraw + SM_RING0), smem_u32(smraw + SM_RING1) };

    const int f    = blockIdx.x;
    const int tid  = threadIdx.x;
    const int warp = tid >> 5;
    const int lane = tid & 31;
    const int qid  = lane >> 2;
    const int tq   = lane & 3;

    const int m_lo = 16 * warp + qid;
    const int m_hi = m_lo + 8;
    const bool v_lo = (m_lo < HW);
    const bool v_hi = (m_hi < HW);
    const int ob_lo = v_lo ? (13 * (m_lo / 11) + (m_lo % 11)) : 143;
    const int ob_hi = v_hi ? (13 * (m_hi / 11) + (m_hi % 11)) : 143;

    {
        const uint4* src = (const uint4*)(g_bf);
        for (int i = tid; i < HALF0_FRAGS / 2; i += 256)
            cp16(ring_u32[0] + i * 16, src + i);
        cp_commit();
    }
    {
        unsigned* Xz = (unsigned*)Xh;
        for (int i = tid; i < XROWS * XSTRIDE / 2; i += 256) Xz[i] = 0u;
    }
    __syncthreads();

    const float* xf = x + (size_t)f * 9 * HW;
    for (int i = tid; i < 9 * HW; i += 256) {
        int ic = i / HW, pix = i % HW;
        int row = 13 * (pix / 11) + (pix % 11) + 14;
        Xh[row * XSTRIDE + ic] = __float2half(xf[i]);
    }
    __half* gout = g_conv_out + (size_t)f * FCK;

    float acc[8][4];

    for (int c = 0; c < 16; ++c) {
        const int L = c >> 1, half = c & 1, buf = c & 1;

        if (c + 1 < 16) {
            const int Ln = (c + 1) >> 1, hn = (c + 1) & 1;
            const uint4* src = (const uint4*)(g_bf + (size_t)Ln * BFRAGS
                                              + (hn ? HALF0_FRAGS : 0));
            const int n16 = (hn ? HALF1_FRAGS : HALF0_FRAGS) / 2;
            const uint32_t dst = ring_u32[1 - buf];
            for (int i = tid; i < n16; i += 256) cp16(dst + i * 16, src + i);
            cp_commit();
            cp_wait<1>();
        } else {
            cp_wait<0>();
        }
        if (half == 0 && tid < 64)
            bias[tid] = (L == 0) ? c0b[tid] : cbs[(L - 1) * 64 + tid];
        __syncthreads();

        if (half == 0) {
#pragma unroll
            for (int n = 0; n < 8; ++n) {
                float b0 = bias[n * 8 + 2 * tq], b1 = bias[n * 8 + 2 * tq + 1];
                acc[n][0] = b0; acc[n][1] = b1; acc[n][2] = b0; acc[n][3] = b1;
            }
        }

        const int KS = (L == 0) ? 1 : 4;
        const int tap0 = half ? 5 : 0;
        const int ntap = half ? 4 : 5;
        const uint2* rb = ring[buf];

        for (int t = 0; t < ntap; ++t) {
            const int tap = tap0 + t;
            const int off = 13 * (tap / 3) + (tap % 3);
            const __half* plo_base = Xh + (ob_lo + off) * XSTRIDE;
            const __half* phi_base = Xh + (ob_hi + off) * XSTRIDE;
            for (int ks = 0; ks < KS; ++ks) {
                const int cb = ks * 16 + 2 * tq;
                unsigned a0 = *(const unsigned*)(plo_base + cb);
                unsigned a1 = *(const unsigned*)(phi_base + cb);
                unsigned a2 = *(const unsigned*)(plo_base + cb + 8);
                unsigned a3 = *(const unsigned*)(phi_base + cb + 8);

                const uint2* bp = rb + ((t * 4 + ks) * 8) * 32 + lane;
#pragma unroll
                for (int n = 0; n < 8; ++n) {
                    uint2 b = bp[n * 32];
                    mma_f16(acc[n], a0, a1, a2, a3, b.x, b.y);
                }
            }
        }

        if (half == 1) {
            __syncthreads();
#pragma unroll
            for (int n = 0; n < 8; ++n) {
                const int oc0 = n * 8 + 2 * tq;
                if (v_lo) {
                    __half h0 = __float2half(fmaxf(acc[n][0], 0.f));
                    __half h1 = __float2half(fmaxf(acc[n][1], 0.f));
                    if (L < 7) {
                        *(unsigned*)(Xh + (ob_lo + 14) * XSTRIDE + oc0) = pack_half2(h0, h1);
                    } else {
                        gout[oc0 * HW + m_lo] = h0;
                        gout[(oc0 + 1) * HW + m_lo] = h1;
                    }
                }
                if (v_hi) {
                    __half h0 = __float2half(fmaxf(acc[n][2], 0.f));
                    __half h1 = __float2half(fmaxf(acc[n][3], 0.f));
                    if (L < 7) {
                        *(unsigned*)(Xh + (ob_hi + 14) * XSTRIDE + oc0) = pack_half2(h0, h1);
                    } else {
                        gout[oc0 * HW + m_hi] = h0;
                        gout[(oc0 + 1) * HW + m_hi] = h1;
                    }
                }
            }
        }
        __syncthreads();
    }
}

// =====================================================================
// Kernel 2: FC GEMM, M=64 per CTA, split-K x4, W fp16 (hi only).
// grid (64, 4), 256 threads. Warp w: mt = w>>1 (16-row tile),
// nh = w&1 (32-col half); 4 n-tiles of 8 per warp.
// =====================================================================
__global__ __launch_bounds__(256)
void fc_mma_kernel()
{
    __shared__ __half As[2][64][24];   // 16 K-cols + pad (48B stride)

    const int m0 = blockIdx.x * 64;
    const int split = blockIdx.y;
    const int ks0 = split * FC_KS_PER;
    const int tid = threadIdx.x;
    const int warp = tid >> 5, lane = tid & 31;
    const int mt = warp >> 1, nh = warp & 1;
    const int qid = lane >> 2, tq = lane & 3;

    const int ar = tid >> 1, ap = tid & 1;   // A loaders: threads 0..127

    float acc[4][4] = {};
    uint4 a_reg;
    uint2 bc[4], bn[4];

    // preload chunk 0
    if (tid < 128) {
        a_reg = *(const uint4*)&g_conv_out[(size_t)(m0 + ar) * FCK + ks0 * 16 + ap * 8];
        *(uint4*)&As[0][ar][ap * 8] = a_reg;
    }
#pragma unroll
    for (int j = 0; j < 4; ++j)
        bc[j] = g_wfc[(size_t)ks0 * 256 + (nh * 4 + j) * 32 + lane];
    __syncthreads();

    for (int i = 0; i < FC_KS_PER; ++i) {
        const int buf = i & 1;
        if (i + 1 < FC_KS_PER) {
            const int ks = ks0 + i + 1;
            if (tid < 128)
                a_reg = *(const uint4*)&g_conv_out[(size_t)(m0 + ar) * FCK + ks * 16 + ap * 8];
#pragma unroll
            for (int j = 0; j < 4; ++j)
                bn[j] = g_wfc[(size_t)ks * 256 + (nh * 4 + j) * 32 + lane];
        }
        {
            const int r0 = mt * 16 + qid;
            const int cb = 2 * tq;
            unsigned a0 = *(const unsigned*)&As[buf][r0][cb];
            unsigned a1 = *(const unsigned*)&As[buf][r0 + 8][cb];
            unsigned a2 = *(const unsigned*)&As[buf][r0][cb + 8];
            unsigned a3 = *(const unsigned*)&As[buf][r0 + 8][cb + 8];
#pragma unroll
            for (int j = 0; j < 4; ++j)
                mma_f16(acc[j], a0, a1, a2, a3, bc[j].x, bc[j].y);
        }
        if (i + 1 < FC_KS_PER) {
            if (tid < 128) *(uint4*)&As[1 - buf][ar][ap * 8] = a_reg;
#pragma unroll
            for (int j = 0; j < 4; ++j) bc[j] = bn[j];
        }
        __syncthreads();
    }

    float* dst = g_fc_part + (size_t)split * FRAMES * 64;
#pragma unroll
    for (int j = 0; j < 4; ++j) {
        const int col = (nh * 4 + j) * 8 + 2 * tq;
#pragma unroll
        for (int hf = 0; hf < 2; ++hf) {
            int m = m0 + mt * 16 + qid + 8 * hf;
            dst[(size_t)m * 64 + col]     = acc[j][2 * hf];
            dst[(size_t)m * 64 + col + 1] = acc[j][2 * hf + 1];
        }
    }
}

// =====================================================================
// Kernel 3: xg = relu(sum(fc partials) + fc_b) @ w_ih^T + b_ih + b_hh
// =====================================================================
__global__ __launch_bounds__(256)
void xgates_kernel(const float* __restrict__ w_ih, const float* __restrict__ fc_b,
                   const float* __restrict__ b_ih, const float* __restrict__ b_hh)
{
    __shared__ float fs[32][64];
    const int f0 = blockIdx.x * 32;
    const int g = threadIdx.x;
    float w[64];
#pragma unroll
    for (int k = 0; k < 64; ++k) w[k] = w_ih[g * 64 + k];
    for (int i = g; i < 32 * 64; i += 256) {
        size_t idx = (size_t)f0 * 64 + i;
        float v = g_fc_part[idx]
                + g_fc_part[(size_t)FRAMES * 64 + idx]
                + g_fc_part[(size_t)2 * FRAMES * 64 + idx]
                + g_fc_part[(size_t)3 * FRAMES * 64 + idx]
                + fc_b[i % 64];
        fs[i / 64][i % 64] = fmaxf(v, 0.f);
    }
    __syncthreads();
    const float bias = b_ih[g] + b_hh[g];
    for (int f = 0; f < 32; ++f) {
        float s = bias;
#pragma unroll
        for (int k = 0; k < 64; ++k) s = fmaf(w[k], fs[f][k], s);
        g_xg[(size_t)(f0 + f) * 256 + g] = s;
    }
}

// =====================================================================
// Kernel 4: recurrent LSTM. 32 CTAs, 512 threads.
// =====================================================================
__global__ __launch_bounds__(512)
void lstm_kernel(const float* __restrict__ w_hh)
{
    __shared__ float h_s[64];
    __shared__ float g_s[256];
    const int b = blockIdx.x;
    const int tid = threadIdx.x;
    const int g = tid >> 1, hh = tid & 1;

    float w[32];
#pragma unroll
    for (int k = 0; k < 32; ++k) w[k] = w_hh[g * 64 + hh * 32 + k];
    float c = 0.f;
    if (tid < 64) h_s[tid] = 0.f;
    __syncthreads();

    const float* xgb = g_xg + (size_t)b * 128 * 256;
    float* lob = g_lstm + (size_t)b * 128 * 64;

    float xnext = (hh == 0) ? xgb[g] : 0.f;
    for (int t = 0; t < 128; ++t) {
        float s1 = 0.f, s2 = 0.f;
        const float* hp = h_s + hh * 32;
#pragma unroll
        for (int k = 0; k < 16; ++k) {
            s1 = fmaf(w[k], hp[k], s1);
            s2 = fmaf(w[k + 16], hp[k + 16], s2);
        }
        float s = xnext + s1 + s2;
        s += __shfl_xor_sync(0xffffffffu, s, 1);
        if (hh == 0) {
            g_s[g] = s;
            if (t < 127) xnext = xgb[(t + 1) * 256 + g];
        }
        __syncthreads();
        if (tid < 64) {
            float ig = fast_sigmoid(g_s[tid]);
            float fg = fast_sigmoid(g_s[64 + tid]);
            float gg = fast_tanh(g_s[128 + tid]);
            float og = fast_sigmoid(g_s[192 + tid]);
            c = fg * c + ig * gg;
            float h = og * fast_tanh(c);
            lob[t * 64 + tid] = h;
            h_s[tid] = h;
        }
        __syncthreads();
    }
}

// =====================================================================
// Kernel 5: fused policy/value heads
// =====================================================================
__global__ __launch_bounds__(256)
void heads_kernel(const float* __restrict__ p1w, const float* __restrict__ p1b,
                  const float* __restrict__ p2w, const float* __restrict__ p2b,
                  const float* __restrict__ v1w, const float* __restrict__ v1b,
                  const float* __restrict__ v2w, const float* __restrict__ v2b,
                  float* __restrict__ out)
{
    __shared__ float h_s[32][64];
    __shared__ float p2s[6 * 128];
    __shared__ float v2s[128];
    __shared__ float u_s[256];

    const int f0 = blockIdx.x * 32;
    const int t = threadIdx.x;

    const float* wsrc = (t < 128) ? (p1w + t * 64) : (v1w + (t - 128) * 64);
    float w[64];
#pragma unroll
    for (int k = 0; k < 64; ++k) w[k] = wsrc[k];
    const float bias = (t < 128) ? p1b[t] : v1b[t - 128];

    for (int i = t; i < 32 * 64; i += 256) h_s[i / 64][i % 64] = g_lstm[(size_t)f0 * 64 + i];
    for (int i = t; i < 768; i += 256) p2s[i] = p2w[i];
    if (t < 128) v2s[t] = v2w[t];
    __syncthreads();

    const int warp = t >> 5, lane = t & 31;
    for (int fi = 0; fi < 32; ++fi) {
        float s = bias;
#pragma unroll
        for (int k = 0; k < 64; ++k) s = fmaf(w[k], h_s[fi][k], s);
        u_s[t] = fmaxf(s, 0.f);
        __syncthreads();

        const int f = f0 + fi;
        if (warp < 6) {
            float s2 = 0.f;
#pragma unroll
            for (int j = 0; j < 4; ++j)
                s2 = fmaf(p2s[warp * 128 + j * 32 + lane], u_s[j * 32 + lane], s2);
            for (int off = 16; off; off >>= 1) s2 += __shfl_down_sync(0xffffffffu, s2, off);
            if (lane == 0) out[f * 6 + warp] = s2 + p2b[warp];
        } else if (warp == 6) {
            float s2 = 0.f;
#pragma unroll
            for (int j = 0; j < 4; ++j)
                s2 = fmaf(v2s[j * 32 + lane], u_s[128 + j * 32 + lane], s2);
            for (int off = 16; off; off >>= 1) s2 += __shfl_down_sync(0xffffffffu, s2, off);
            if (lane == 0) out[FRAMES * 6 + f] = s2 + v2b[0];
        }
        __syncthreads();
    }
}

// =====================================================================
extern "C" void kernel_launch(void* const* d_in, const int* in_sizes, int n_in,
                              void* d_out, int out_size)
{
    const float* x    = (const float*)d_in[0];
    const float* c0w  = (const float*)d_in[1];
    const float* c0b  = (const float*)d_in[2];
    const float* cws  = (const float*)d_in[3];
    const float* cbs  = (const float*)d_in[4];
    const float* fcw  = (const float*)d_in[5];
    const float* fcb  = (const float*)d_in[6];
    const float* wih  = (const float*)d_in[7];
    const float* whh  = (const float*)d_in[8];
    const float* bih  = (const float*)d_in[9];
    const float* bhh  = (const float*)d_in[10];
    const float* p1w  = (const float*)d_in[11];
    const float* p1b  = (const float*)d_in[12];
    const float* p2w  = (const float*)d_in[13];
    const float* p2b  = (const float*)d_in[14];
    const float* v1w  = (const float*)d_in[15];
    const float* v1b  = (const float*)d_in[16];
    const float* v2w  = (const float*)d_in[17];
    const float* v2b  = (const float*)d_in[18];
    float* out = (float*)d_out;

    cudaFuncSetAttribute(conv_mma_kernel,
                         cudaFuncAttributeMaxDynamicSharedMemorySize, SM_TOTAL);

    bfrag_prep<<<288, 256>>>(c0w, cws);
    wfrag_prep<<<(FC_KS * 8 * 32 + 255) / 256, 256>>>(fcw);
    conv_mma_kernel<<<FRAMES, 256, SM_TOTAL>>>(x, c0b, cbs);
    fc_mma_kernel<<<dim3(FRAMES / 64, FC_SPLITS), 256>>>();
    xgates_kernel<<<FRAMES / 32, 256>>>(wih, fcb, bih, bhh);
    lstm_kernel<<<32, 512>>>(whh);
    heads_kernel<<<FRAMES / 32, 256>>>(p1w, p1b, p2w, p2b, v1w, v1b, v2w, v2b, out);
}